// round 12
// baseline (speedup 1.0000x reference)
#include <cuda_runtime.h>

constexpr int Bc = 512;
constexpr int Lc = 200;
constexpr int Ec = 64;

// ---------------- smem layout (floats) ----------------
constexpr int WTP    = 68;                        // wT[48][68]: wT[c][j]
constexpr int WT_OFF = 0;
constexpr int XSS    = 68;                        // xs[128][68] row-major
constexpr int XS_OFF = WT_OFF + 48 * WTP;         // 3264
constexpr int KTS    = 208;                       // kt[16][208]: kt[d][t]
constexpr int KT_OFF = XS_OFF + 128 * XSS;        // 11968
constexpr int QS_OFF = KT_OFF + 16 * KTS;         // q[200][16] (pre-scaled by 0.25*log2e)
constexpr int VS_OFF = QS_OFF + Lc * 16;          // v[200][16]
constexpr int WC_OFF = VS_OFF + Lc * 16;          // col sums [200]
constexpr int SP_OFF = WC_OFF + Lc + 8;           // partials [16][16]
constexpr int SM1_F  = SP_OFF + 256;              // 22160 floats = 88640 B

__device__ __forceinline__ float ex2f(float x) {
    float y;
    asm("ex2.approx.ftz.f32 %0, %1;" : "=f"(y) : "f"(x));
    return y;
}

extern __shared__ float sw[];

__global__ void __launch_bounds__(256, 2)
attn_head_kernel(const float* __restrict__ input,
                 const int* __restrict__ mask,
                 const float* __restrict__ pos_enc,
                 const float* __restrict__ Wk, const float* __restrict__ bk,
                 const float* __restrict__ Wv, const float* __restrict__ bv,
                 const float* __restrict__ Wq, const float* __restrict__ bq,
                 const float* __restrict__ Wf, const float* __restrict__ bf,
                 float* __restrict__ out) {
    const int tid  = threadIdx.x;
    const int lane = tid & 31;
    const int wid  = tid >> 5;
    const int b    = blockIdx.x >> 2;
    const int h    = blockIdx.x & 3;

    // ---- len (prefix mask; mask is int32) ----
    int pred = (tid < Lc) && (mask[(size_t)b * Lc + tid] != 0);
    const int len = __syncthreads_count(pred);

    // ---- phase 0: weights transposed: wT[c][j], c = m*16+i ----
    for (int idx = tid; idx < 64 * 48; idx += 256) {
        int c = idx >> 6, j = idx & 63;
        int m = c >> 4, i = c & 15;
        const float* Wm = (m == 0) ? Wk : ((m == 1) ? Wv : Wq);
        sw[WT_OFF + c * WTP + j] = Wm[(h * 16 + i) * 64 + j];
    }
    if (tid < Lc) sw[WC_OFF + tid] = 0.0f;
    __syncthreads();

    // ---- phase 1 (round-10 verbatim): register-tiled GEMM [len,64]x[64,48] ----
    const int rowgrp = tid >> 3;          // 0..31
    const int colgrp = tid & 7;           // 0..7
    const float QSC = 0.36067376022224085f;   // 0.25 * log2(e)

    float bias[6];
#pragma unroll
    for (int s = 0; s < 6; s++) {
        int c = colgrp + 8 * s, m = c >> 4, i = c & 15;
        bias[s] = (m == 0) ? bk[h * 16 + i] : ((m == 1) ? bv[h * 16 + i] : bq[h * 16 + i]);
    }

    const int ntiles = (len + 127) >> 7;
    for (int tile = 0; tile < ntiles; tile++) {
        const int tb = tile * 128;
        const float4* in4 = (const float4*)(input + ((size_t)b * Lc + tb) * Ec);
        const float4* pe4 = (const float4*)(pos_enc + (size_t)tb * Ec);
#pragma unroll
        for (int v = 0; v < 8; v++) {
            int f = tid + v * 256;            // 0..2047
            int t = f >> 4, e0 = (f & 15) * 4;
            float4 val = make_float4(0.f, 0.f, 0.f, 0.f);
            if (tb + t < Lc) {
                float4 a = in4[f], p = pe4[f];
                val = make_float4(a.x + p.x, a.y + p.y, a.z + p.z, a.w + p.w);
            }
            *(float4*)(sw + XS_OFF + t * XSS + e0) = val;
        }
        __syncthreads();

        if (tb + rowgrp < len) {
            float acc[4][6];
#pragma unroll
            for (int rr = 0; rr < 4; rr++)
#pragma unroll
                for (int s = 0; s < 6; s++) acc[rr][s] = 0.f;

#pragma unroll
            for (int j4 = 0; j4 < 64; j4 += 4) {
                float4 xv[4];
#pragma unroll
                for (int rr = 0; rr < 4; rr++)
                    xv[rr] = *(const float4*)(sw + XS_OFF + (rowgrp + 32 * rr) * XSS + j4);
#pragma unroll
                for (int s = 0; s < 6; s++) {
                    float4 wq = *(const float4*)(sw + WT_OFF + (colgrp + 8 * s) * WTP + j4);
#pragma unroll
                    for (int rr = 0; rr < 4; rr++) {
                        acc[rr][s] = fmaf(xv[rr].x, wq.x, acc[rr][s]);
                        acc[rr][s] = fmaf(xv[rr].y, wq.y, acc[rr][s]);
                        acc[rr][s] = fmaf(xv[rr].z, wq.z, acc[rr][s]);
                        acc[rr][s] = fmaf(xv[rr].w, wq.w, acc[rr][s]);
                    }
                }
            }

#pragma unroll
            for (int rr = 0; rr < 4; rr++) {
                int t = tb + rowgrp + 32 * rr;
                if (t < len) {
#pragma unroll
                    for (int s = 0; s < 6; s++) {
                        int c = colgrp + 8 * s;
                        float v = acc[rr][s] + bias[s];
                        if (c < 16)       sw[KT_OFF + c * KTS + t] = v;
                        else if (c < 32)  sw[VS_OFF + t * 16 + (c - 16)] = v;
                        else              sw[QS_OFF + t * 16 + (c - 32)] = v * QSC;
                    }
                }
            }
        }
        __syncthreads();
    }

    // ---- phase 2: scores + softmax + column sums; 128-key blocks, LDS.128 kt ----
    // lane owns keys k = kb*128 + lane*4 + {0..3}; 4 query rows per warp iteration
    const int nb2 = (len + 127) >> 7;            // 1..2 k-blocks of 128
    float wacc[2][4];
#pragma unroll
    for (int kb = 0; kb < 2; kb++)
#pragma unroll
        for (int i = 0; i < 4; i++) wacc[kb][i] = 0.f;

    for (int qb = wid * 4; qb < len; qb += 32) {
        float qv[4][16];
#pragma unroll
        for (int qq = 0; qq < 4; qq++) {
            int q = qb + qq; q = (q < len) ? q : 0;
            const float4* p = (const float4*)(sw + QS_OFF + q * 16);
#pragma unroll
            for (int jj = 0; jj < 4; jj++) {
                float4 v = p[jj];
                qv[qq][4 * jj + 0] = v.x; qv[qq][4 * jj + 1] = v.y;
                qv[qq][4 * jj + 2] = v.z; qv[qq][4 * jj + 3] = v.w;
            }
        }

        float aa[2][4][4];                        // [kb][q][key] acc -> exp in place
        float z[4] = {0.f, 0.f, 0.f, 0.f};
#pragma unroll
        for (int kb = 0; kb < 2; kb++) {
            if (kb < nb2) {
                const int k0 = kb * 128 + lane * 4;
                const float* kp = sw + KT_OFF + k0;
#pragma unroll
                for (int qq = 0; qq < 4; qq++)
#pragma unroll
                    for (int i = 0; i < 4; i++) aa[kb][qq][i] = 0.f;
#pragma unroll
                for (int j = 0; j < 16; j++) {
                    float4 kt4 = *(const float4*)(kp + j * KTS);
#pragma unroll
                    for (int qq = 0; qq < 4; qq++) {
                        aa[kb][qq][0] = fmaf(kt4.x, qv[qq][j], aa[kb][qq][0]);
                        aa[kb][qq][1] = fmaf(kt4.y, qv[qq][j], aa[kb][qq][1]);
                        aa[kb][qq][2] = fmaf(kt4.z, qv[qq][j], aa[kb][qq][2]);
                        aa[kb][qq][3] = fmaf(kt4.w, qv[qq][j], aa[kb][qq][3]);
                    }
                }
                const bool ok0 = (k0 + 0) < len;
                const bool ok1 = (k0 + 1) < len;
                const bool ok2 = (k0 + 2) < len;
                const bool ok3 = (k0 + 3) < len;
#pragma unroll
                for (int qq = 0; qq < 4; qq++) {
                    float e0 = ok0 ? ex2f(aa[kb][qq][0]) : 0.f;
                    float e1 = ok1 ? ex2f(aa[kb][qq][1]) : 0.f;
                    float e2 = ok2 ? ex2f(aa[kb][qq][2]) : 0.f;
                    float e3 = ok3 ? ex2f(aa[kb][qq][3]) : 0.f;
                    aa[kb][qq][0] = e0; aa[kb][qq][1] = e1;
                    aa[kb][qq][2] = e2; aa[kb][qq][3] = e3;
                    z[qq] += (e0 + e1) + (e2 + e3);
                }
            } else {
#pragma unroll
                for (int qq = 0; qq < 4; qq++)
#pragma unroll
                    for (int i = 0; i < 4; i++) aa[kb][qq][i] = 0.f;
            }
        }

#pragma unroll
        for (int o = 16; o; o >>= 1) {
            z[0] += __shfl_xor_sync(0xffffffffu, z[0], o);
            z[1] += __shfl_xor_sync(0xffffffffu, z[1], o);
            z[2] += __shfl_xor_sync(0xffffffffu, z[2], o);
            z[3] += __shfl_xor_sync(0xffffffffu, z[3], o);
        }
        float inv[4];
#pragma unroll
        for (int qq = 0; qq < 4; qq++)
            inv[qq] = (qb + qq < len) ? __fdividef(1.0f, z[qq]) : 0.0f;
#pragma unroll
        for (int kb = 0; kb < 2; kb++) {
            if (kb < nb2) {
#pragma unroll
                for (int qq = 0; qq < 4; qq++) {
#pragma unroll
                    for (int i = 0; i < 4; i++)
                        wacc[kb][i] = fmaf(aa[kb][qq][i], inv[qq], wacc[kb][i]);
                }
            }
        }
    }

#pragma unroll
    for (int kb = 0; kb < 2; kb++) {
        if (kb < nb2) {
            int k = kb * 128 + lane * 4;
#pragma unroll
            for (int i = 0; i < 4; i++)
                if (k + i < Lc) atomicAdd(&sw[WC_OFF + k + i], wacc[kb][i]);
        }
    }
    __syncthreads();

    // ---- phase 3: S[c] = sum_k wc[k] * V[k][c] ----
    {
        const int c = tid & 15, part = tid >> 4;
        float acc = 0.f;
        for (int k = part; k < len; k += 16)
            acc = fmaf(sw[WC_OFF + k], sw[VS_OFF + k * 16 + c], acc);
        sw[SP_OFF + part * 16 + c] = acc;
    }
    __syncthreads();
    if (tid < 16) {
        float s = 0.f;
#pragma unroll
        for (int p = 0; p < 16; p++) s += sw[SP_OFF + p * 16 + tid];
        sw[SP_OFF + tid] = s;   // own slot: safe (only p=0 term read by self)
    }
    __syncthreads();

    // ---- phase 4 (fused): out[b][e] += inv*(S_head . Wf[e, h*16:]) (+ bf term on h==0) ----
    if (tid < 64) {
        float acc = 0.f;
        const float* wfr = Wf + tid * 64 + h * 16;
#pragma unroll
        for (int i = 0; i < 16; i++)
            acc = fmaf(sw[SP_OFF + i], wfr[i], acc);
        const float lenf = (float)len;
        const float invd = 1.0f / (lenf + 1e-8f);
        float val = acc * invd;
        if (h == 0) val = fmaf(bf[tid], lenf * invd, val);
        atomicAdd(out + b * 64 + tid, val);
    }
}

extern "C" void kernel_launch(void* const* d_in, const int* in_sizes, int n_in,
                              void* d_out, int out_size) {
    const float* input   = (const float*)d_in[0];
    const int*   mask    = (const int*)d_in[1];
    const float* pos_enc = (const float*)d_in[2];
    const float* Wk      = (const float*)d_in[3];
    const float* bk      = (const float*)d_in[4];
    const float* Wv      = (const float*)d_in[5];
    const float* bv      = (const float*)d_in[6];
    const float* Wq      = (const float*)d_in[7];
    const float* bq      = (const float*)d_in[8];
    const float* Wf      = (const float*)d_in[9];
    const float* bf      = (const float*)d_in[10];
    float* out           = (float*)d_out;

    cudaMemsetAsync(out, 0, (size_t)Bc * Ec * sizeof(float), 0);

    const size_t smem1 = (size_t)SM1_F * sizeof(float);
    cudaFuncSetAttribute(attn_head_kernel,
                         cudaFuncAttributeMaxDynamicSharedMemorySize, (int)smem1);
    attn_head_kernel<<<Bc * 4, 256, smem1>>>(input, mask, pos_enc,
                                             Wk, bk, Wv, bv, Wq, bq, Wf, bf, out);
}

// round 13
// speedup vs baseline: 1.0776x; 1.0776x over previous
#include <cuda_runtime.h>

constexpr int Bc = 512;
constexpr int Lc = 200;
constexpr int Ec = 64;

// ---------------- smem layout (floats) ----------------
constexpr int WTP    = 68;                        // wT[48][68]: wT[c][j]
constexpr int WT_OFF = 0;
constexpr int XSS    = 68;                        // xs[128][68] row-major
constexpr int XS_OFF = WT_OFF + 48 * WTP;         // 3264
constexpr int KTS    = 208;                       // kt[16][208]: kt[d][t]
constexpr int KT_OFF = XS_OFF + 128 * XSS;        // 11968
constexpr int QS_OFF = KT_OFF + 16 * KTS;         // q[200][16] (pre-scaled by 0.25*log2e)
constexpr int VS_OFF = QS_OFF + Lc * 16;          // v[200][16]
constexpr int WC_OFF = VS_OFF + Lc * 16;          // col sums [200]
constexpr int SP_OFF = WC_OFF + Lc + 8;           // partials [16][16]
constexpr int SM1_F  = SP_OFF + 256;              // 22160 floats = 88640 B

__device__ __forceinline__ float ex2f(float x) {
    float y;
    asm("ex2.approx.ftz.f32 %0, %1;" : "=f"(y) : "f"(x));
    return y;
}

extern __shared__ float sw[];

// phase-1 tile body: NR rows per thread (rows rowgrp + 32*rr), 6 cols
template <int NR>
__device__ __forceinline__ void proj_tile(int rowgrp, int colgrp, int tb, int len,
                                          const float* bias, float QSC) {
    float acc[NR][6];
#pragma unroll
    for (int rr = 0; rr < NR; rr++)
#pragma unroll
        for (int s = 0; s < 6; s++) acc[rr][s] = 0.f;

#pragma unroll
    for (int j4 = 0; j4 < 64; j4 += 4) {
        float4 xv[NR];
#pragma unroll
        for (int rr = 0; rr < NR; rr++)
            xv[rr] = *(const float4*)(sw + XS_OFF + (rowgrp + 32 * rr) * XSS + j4);
#pragma unroll
        for (int s = 0; s < 6; s++) {
            float4 wq = *(const float4*)(sw + WT_OFF + (colgrp + 8 * s) * WTP + j4);
#pragma unroll
            for (int rr = 0; rr < NR; rr++) {
                acc[rr][s] = fmaf(xv[rr].x, wq.x, acc[rr][s]);
                acc[rr][s] = fmaf(xv[rr].y, wq.y, acc[rr][s]);
                acc[rr][s] = fmaf(xv[rr].z, wq.z, acc[rr][s]);
                acc[rr][s] = fmaf(xv[rr].w, wq.w, acc[rr][s]);
            }
        }
    }

#pragma unroll
    for (int rr = 0; rr < NR; rr++) {
        int t = tb + rowgrp + 32 * rr;
        if (t < len) {
#pragma unroll
            for (int s = 0; s < 6; s++) {
                int c = colgrp + 8 * s;
                float v = acc[rr][s] + bias[s];
                if (c < 16)       sw[KT_OFF + c * KTS + t] = v;
                else if (c < 32)  sw[VS_OFF + t * 16 + (c - 16)] = v;
                else              sw[QS_OFF + t * 16 + (c - 32)] = v * QSC;
            }
        }
    }
}

__global__ void __launch_bounds__(256, 2)
attn_head_kernel(const float* __restrict__ input,
                 const int* __restrict__ mask,
                 const float* __restrict__ pos_enc,
                 const float* __restrict__ Wk, const float* __restrict__ bk,
                 const float* __restrict__ Wv, const float* __restrict__ bv,
                 const float* __restrict__ Wq, const float* __restrict__ bq,
                 const float* __restrict__ Wf, const float* __restrict__ bf,
                 float* __restrict__ out) {
    const int tid  = threadIdx.x;
    const int lane = tid & 31;
    const int wid  = tid >> 5;
    const int b    = blockIdx.x >> 2;
    const int h    = blockIdx.x & 3;

    // ---- len (prefix mask; mask is int32) ----
    int pred = (tid < Lc) && (mask[(size_t)b * Lc + tid] != 0);
    const int len = __syncthreads_count(pred);

    // ---- phase 0: weights transposed: wT[c][j], c = m*16+i ----
    for (int idx = tid; idx < 64 * 48; idx += 256) {
        int c = idx >> 6, j = idx & 63;
        int m = c >> 4, i = c & 15;
        const float* Wm = (m == 0) ? Wk : ((m == 1) ? Wv : Wq);
        sw[WT_OFF + c * WTP + j] = Wm[(h * 16 + i) * 64 + j];
    }
    if (tid < Lc) sw[WC_OFF + tid] = 0.0f;
    __syncthreads();

    // ---- phase 1: register-tiled GEMM, len-adaptive row count ----
    const int rowgrp = tid >> 3;          // 0..31
    const int colgrp = tid & 7;           // 0..7
    const float QSC = 0.36067376022224085f;   // 0.25 * log2(e)

    float bias[6];
#pragma unroll
    for (int s = 0; s < 6; s++) {
        int c = colgrp + 8 * s, m = c >> 4, i = c & 15;
        bias[s] = (m == 0) ? bk[h * 16 + i] : ((m == 1) ? bv[h * 16 + i] : bq[h * 16 + i]);
    }

    const int ntiles = (len + 127) >> 7;
    for (int tile = 0; tile < ntiles; tile++) {
        const int tb = tile * 128;
        int R = len - tb; if (R > 128) R = 128;
        const int fmax = R << 4;              // float4 slots to stage
        const float4* in4 = (const float4*)(input + ((size_t)b * Lc + tb) * Ec);
        const float4* pe4 = (const float4*)(pos_enc + (size_t)tb * Ec);
#pragma unroll
        for (int v = 0; v < 8; v++) {
            int f = tid + v * 256;            // 0..2047
            if (f < fmax) {
                int t = f >> 4, e0 = (f & 15) * 4;
                float4 a = in4[f], p = pe4[f];
                *(float4*)(sw + XS_OFF + t * XSS + e0) =
                    make_float4(a.x + p.x, a.y + p.y, a.z + p.z, a.w + p.w);
            }
        }
        __syncthreads();

        if (rowgrp < R) {
            const int nr = (R + 31) >> 5;     // rows-per-thread this tile (1..4)
            switch (nr) {
                case 1: proj_tile<1>(rowgrp, colgrp, tb, len, bias, QSC); break;
                case 2: proj_tile<2>(rowgrp, colgrp, tb, len, bias, QSC); break;
                case 3: proj_tile<3>(rowgrp, colgrp, tb, len, bias, QSC); break;
                default: proj_tile<4>(rowgrp, colgrp, tb, len, bias, QSC); break;
            }
        }
        __syncthreads();
    }

    // ---- phase 2 (round-10 verbatim): scores + softmax + column sums ----
    // lane owns keys k = kb*64 + lane*2 + {0,1}; 4 query rows per warp iteration
    const int nb = (len + 63) >> 6;              // 1..4 k-blocks of 64
    float wacc[4][2];
#pragma unroll
    for (int kb = 0; kb < 4; kb++) { wacc[kb][0] = 0.f; wacc[kb][1] = 0.f; }

    for (int qb = wid * 4; qb < len; qb += 32) {
        float qv[4][16];
#pragma unroll
        for (int qq = 0; qq < 4; qq++) {
            int q = qb + qq; q = (q < len) ? q : 0;
            const float4* p = (const float4*)(sw + QS_OFF + q * 16);
#pragma unroll
            for (int jj = 0; jj < 4; jj++) {
                float4 v = p[jj];
                qv[qq][4 * jj + 0] = v.x; qv[qq][4 * jj + 1] = v.y;
                qv[qq][4 * jj + 2] = v.z; qv[qq][4 * jj + 3] = v.w;
            }
        }

        float ee[4][4][2];                        // [kb][q][key]
        float z[4] = {0.f, 0.f, 0.f, 0.f};
#pragma unroll
        for (int kb = 0; kb < 4; kb++) {
            if (kb < nb) {
                const int k0 = kb * 64 + lane * 2;
                const float* kp = sw + KT_OFF + k0;
                float a0[4], a1[4];
#pragma unroll
                for (int qq = 0; qq < 4; qq++) { a0[qq] = 0.f; a1[qq] = 0.f; }
#pragma unroll
                for (int j = 0; j < 16; j++) {
                    float2 kt2 = *(const float2*)(kp + j * KTS);
#pragma unroll
                    for (int qq = 0; qq < 4; qq++) {
                        a0[qq] = fmaf(kt2.x, qv[qq][j], a0[qq]);
                        a1[qq] = fmaf(kt2.y, qv[qq][j], a1[qq]);
                    }
                }
                const bool ok0 = (k0 + 0) < len;
                const bool ok1 = (k0 + 1) < len;
#pragma unroll
                for (int qq = 0; qq < 4; qq++) {
                    float e0 = ok0 ? ex2f(a0[qq]) : 0.f;
                    float e1 = ok1 ? ex2f(a1[qq]) : 0.f;
                    ee[kb][qq][0] = e0; ee[kb][qq][1] = e1;
                    z[qq] += e0 + e1;
                }
            } else {
#pragma unroll
                for (int qq = 0; qq < 4; qq++) { ee[kb][qq][0] = 0.f; ee[kb][qq][1] = 0.f; }
            }
        }

#pragma unroll
        for (int o = 16; o; o >>= 1) {
            z[0] += __shfl_xor_sync(0xffffffffu, z[0], o);
            z[1] += __shfl_xor_sync(0xffffffffu, z[1], o);
            z[2] += __shfl_xor_sync(0xffffffffu, z[2], o);
            z[3] += __shfl_xor_sync(0xffffffffu, z[3], o);
        }
        float inv[4];
#pragma unroll
        for (int qq = 0; qq < 4; qq++)
            inv[qq] = (qb + qq < len) ? __fdividef(1.0f, z[qq]) : 0.0f;
#pragma unroll
        for (int kb = 0; kb < 4; kb++) {
            if (kb < nb) {
#pragma unroll
                for (int qq = 0; qq < 4; qq++) {
                    wacc[kb][0] = fmaf(ee[kb][qq][0], inv[qq], wacc[kb][0]);
                    wacc[kb][1] = fmaf(ee[kb][qq][1], inv[qq], wacc[kb][1]);
                }
            }
        }
    }

#pragma unroll
    for (int kb = 0; kb < 4; kb++) {
        if (kb < nb) {
            int k = kb * 64 + lane * 2;
            if (k < Lc)     atomicAdd(&sw[WC_OFF + k],     wacc[kb][0]);
            if (k + 1 < Lc) atomicAdd(&sw[WC_OFF + k + 1], wacc[kb][1]);
        }
    }
    __syncthreads();

    // ---- phase 3: S[c] = sum_k wc[k] * V[k][c] ----
    {
        const int c = tid & 15, part = tid >> 4;
        float acc = 0.f;
        for (int k = part; k < len; k += 16)
            acc = fmaf(sw[WC_OFF + k], sw[VS_OFF + k * 16 + c], acc);
        sw[SP_OFF + part * 16 + c] = acc;
    }
    __syncthreads();
    if (tid < 16) {
        float s = 0.f;
#pragma unroll
        for (int p = 0; p < 16; p++) s += sw[SP_OFF + p * 16 + tid];
        sw[SP_OFF + tid] = s;   // own slot: safe (only p=0 term read by self)
    }
    __syncthreads();

    // ---- phase 4 (fused): out[b][e] += inv*(S_head . Wf[e, h*16:]) (+ bf term on h==0) ----
    if (tid < 64) {
        float acc = 0.f;
        const float* wfr = Wf + tid * 64 + h * 16;
#pragma unroll
        for (int i = 0; i < 16; i++)
            acc = fmaf(sw[SP_OFF + i], wfr[i], acc);
        const float lenf = (float)len;
        const float invd = 1.0f / (lenf + 1e-8f);
        float val = acc * invd;
        if (h == 0) val = fmaf(bf[tid], lenf * invd, val);
        atomicAdd(out + b * 64 + tid, val);
    }
}

extern "C" void kernel_launch(void* const* d_in, const int* in_sizes, int n_in,
                              void* d_out, int out_size) {
    const float* input   = (const float*)d_in[0];
    const int*   mask    = (const int*)d_in[1];
    const float* pos_enc = (const float*)d_in[2];
    const float* Wk      = (const float*)d_in[3];
    const float* bk      = (const float*)d_in[4];
    const float* Wv      = (const float*)d_in[5];
    const float* bv      = (const float*)d_in[6];
    const float* Wq      = (const float*)d_in[7];
    const float* bq      = (const float*)d_in[8];
    const float* Wf      = (const float*)d_in[9];
    const float* bf      = (const float*)d_in[10];
    float* out           = (float*)d_out;

    cudaMemsetAsync(out, 0, (size_t)Bc * Ec * sizeof(float), 0);

    const size_t smem1 = (size_t)SM1_F * sizeof(float);
    cudaFuncSetAttribute(attn_head_kernel,
                         cudaFuncAttributeMaxDynamicSharedMemorySize, (int)smem1);
    attn_head_kernel<<<Bc * 4, 256, smem1>>>(input, mask, pos_enc,
                                             Wk, bk, Wv, bv, Wq, bq, Wf, bf, out);
}

// round 14
// speedup vs baseline: 1.1055x; 1.0259x over previous
#include <cuda_runtime.h>

constexpr int Bc = 512;
constexpr int Lc = 200;
constexpr int Ec = 64;

// ---------------- smem layout (floats) ----------------
constexpr int WTP    = 68;                        // wT[48][68]: wT[c][j]
constexpr int WT_OFF = 0;
constexpr int XSS    = 68;                        // xs[128][68] row-major
constexpr int XS_OFF = WT_OFF + 48 * WTP;         // 3264
constexpr int KTS    = 208;                       // kt[16][208]: kt[d][t]
constexpr int KT_OFF = XS_OFF + 128 * XSS;        // 11968
constexpr int QS_OFF = KT_OFF + 16 * KTS;         // q[200][16] (pre-scaled by 0.25*log2e)
constexpr int VS_OFF = QS_OFF + Lc * 16;          // v[200][16]
constexpr int WC_OFF = VS_OFF + Lc * 16;          // col sums [200]
constexpr int SP_OFF = WC_OFF + Lc + 8;           // partials [16][16]
constexpr int SM1_F  = SP_OFF + 256;              // 22160 floats = 88640 B

__device__ int g_len[Bc];
__device__ int g_order[Bc];

__device__ __forceinline__ float ex2f(float x) {
    float y;
    asm("ex2.approx.ftz.f32 %0, %1;" : "=f"(y) : "f"(x));
    return y;
}

// ---- pre-kernel 1: per-batch valid length ----
__global__ void len_kernel(const int* __restrict__ mask) {
    int b = blockIdx.x;
    int pred = (threadIdx.x < Lc) && (mask[(size_t)b * Lc + threadIdx.x] != 0);
    int len = __syncthreads_count(pred);
    if (threadIdx.x == 0) g_len[b] = len;
}

// ---- pre-kernel 2: counting sort, descending len ----
__global__ void sort_kernel() {
    __shared__ int hist[Lc + 1];
    __shared__ int offs[Lc + 1];
    const int tid = threadIdx.x;
    for (int i = tid; i <= Lc; i += 256) hist[i] = 0;
    __syncthreads();
    for (int b = tid; b < Bc; b += 256) atomicAdd(&hist[g_len[b]], 1);
    __syncthreads();
    if (tid == 0) {
        int acc = 0;
        for (int l = Lc; l >= 0; l--) { offs[l] = acc; acc += hist[l]; }
    }
    __syncthreads();
    for (int b = tid; b < Bc; b += 256) {
        int pos = atomicAdd(&offs[g_len[b]], 1);
        g_order[pos] = b;
    }
}

extern __shared__ float sw[];

// phase-1 tile body: NR rows per thread (rows rowgrp + 32*rr), 6 cols
template <int NR>
__device__ __forceinline__ void proj_tile(int rowgrp, int colgrp, int tb, int len,
                                          const float* bias, float QSC) {
    float acc[NR][6];
#pragma unroll
    for (int rr = 0; rr < NR; rr++)
#pragma unroll
        for (int s = 0; s < 6; s++) acc[rr][s] = 0.f;

#pragma unroll
    for (int j4 = 0; j4 < 64; j4 += 4) {
        float4 xv[NR];
#pragma unroll
        for (int rr = 0; rr < NR; rr++)
            xv[rr] = *(const float4*)(sw + XS_OFF + (rowgrp + 32 * rr) * XSS + j4);
#pragma unroll
        for (int s = 0; s < 6; s++) {
            float4 wq = *(const float4*)(sw + WT_OFF + (colgrp + 8 * s) * WTP + j4);
#pragma unroll
            for (int rr = 0; rr < NR; rr++) {
                acc[rr][s] = fmaf(xv[rr].x, wq.x, acc[rr][s]);
                acc[rr][s] = fmaf(xv[rr].y, wq.y, acc[rr][s]);
                acc[rr][s] = fmaf(xv[rr].z, wq.z, acc[rr][s]);
                acc[rr][s] = fmaf(xv[rr].w, wq.w, acc[rr][s]);
            }
        }
    }

#pragma unroll
    for (int rr = 0; rr < NR; rr++) {
        int t = tb + rowgrp + 32 * rr;
        if (t < len) {
#pragma unroll
            for (int s = 0; s < 6; s++) {
                int c = colgrp + 8 * s;
                float v = acc[rr][s] + bias[s];
                if (c < 16)       sw[KT_OFF + c * KTS + t] = v;
                else if (c < 32)  sw[VS_OFF + t * 16 + (c - 16)] = v;
                else              sw[QS_OFF + t * 16 + (c - 32)] = v * QSC;
            }
        }
    }
}

__global__ void __launch_bounds__(256, 2)
attn_head_kernel(const float* __restrict__ input,
                 const float* __restrict__ pos_enc,
                 const float* __restrict__ Wk, const float* __restrict__ bk,
                 const float* __restrict__ Wv, const float* __restrict__ bv,
                 const float* __restrict__ Wq, const float* __restrict__ bq,
                 const float* __restrict__ Wf, const float* __restrict__ bf,
                 float* __restrict__ out) {
    const int tid  = threadIdx.x;
    const int lane = tid & 31;
    const int wid  = tid >> 5;
    const int b    = g_order[blockIdx.x >> 2];   // longest-first schedule
    const int h    = blockIdx.x & 3;
    const int len  = g_len[b];

    // ---- phase 0: weights transposed: wT[c][j], c = m*16+i ----
    for (int idx = tid; idx < 64 * 48; idx += 256) {
        int c = idx >> 6, j = idx & 63;
        int m = c >> 4, i = c & 15;
        const float* Wm = (m == 0) ? Wk : ((m == 1) ? Wv : Wq);
        sw[WT_OFF + c * WTP + j] = Wm[(h * 16 + i) * 64 + j];
    }
    if (tid < Lc) sw[WC_OFF + tid] = 0.0f;
    __syncthreads();

    // ---- phase 1: register-tiled GEMM, len-adaptive row count ----
    const int rowgrp = tid >> 3;          // 0..31
    const int colgrp = tid & 7;           // 0..7
    const float QSC = 0.36067376022224085f;   // 0.25 * log2(e)

    float bias[6];
#pragma unroll
    for (int s = 0; s < 6; s++) {
        int c = colgrp + 8 * s, m = c >> 4, i = c & 15;
        bias[s] = (m == 0) ? bk[h * 16 + i] : ((m == 1) ? bv[h * 16 + i] : bq[h * 16 + i]);
    }

    const int ntiles = (len + 127) >> 7;
    for (int tile = 0; tile < ntiles; tile++) {
        const int tb = tile * 128;
        int R = len - tb; if (R > 128) R = 128;
        const int fmax = R << 4;
        const float4* in4 = (const float4*)(input + ((size_t)b * Lc + tb) * Ec);
        const float4* pe4 = (const float4*)(pos_enc + (size_t)tb * Ec);
#pragma unroll
        for (int v = 0; v < 8; v++) {
            int f = tid + v * 256;
            if (f < fmax) {
                int t = f >> 4, e0 = (f & 15) * 4;
                float4 a = in4[f], p = pe4[f];
                *(float4*)(sw + XS_OFF + t * XSS + e0) =
                    make_float4(a.x + p.x, a.y + p.y, a.z + p.z, a.w + p.w);
            }
        }
        __syncthreads();

        if (rowgrp < R) {
            const int nr = (R + 31) >> 5;
            switch (nr) {
                case 1: proj_tile<1>(rowgrp, colgrp, tb, len, bias, QSC); break;
                case 2: proj_tile<2>(rowgrp, colgrp, tb, len, bias, QSC); break;
                case 3: proj_tile<3>(rowgrp, colgrp, tb, len, bias, QSC); break;
                default: proj_tile<4>(rowgrp, colgrp, tb, len, bias, QSC); break;
            }
        }
        __syncthreads();
    }

    // ---- phase 2: scores + softmax + column sums ----
    const int nb = (len + 63) >> 6;
    float wacc[4][2];
#pragma unroll
    for (int kb = 0; kb < 4; kb++) { wacc[kb][0] = 0.f; wacc[kb][1] = 0.f; }

    for (int qb = wid * 4; qb < len; qb += 32) {
        float qv[4][16];
#pragma unroll
        for (int qq = 0; qq < 4; qq++) {
            int q = qb + qq; q = (q < len) ? q : 0;
            const float4* p = (const float4*)(sw + QS_OFF + q * 16);
#pragma unroll
            for (int jj = 0; jj < 4; jj++) {
                float4 v = p[jj];
                qv[qq][4 * jj + 0] = v.x; qv[qq][4 * jj + 1] = v.y;
                qv[qq][4 * jj + 2] = v.z; qv[qq][4 * jj + 3] = v.w;
            }
        }

        float ee[4][4][2];
        float z[4] = {0.f, 0.f, 0.f, 0.f};
#pragma unroll
        for (int kb = 0; kb < 4; kb++) {
            if (kb < nb) {
                const int k0 = kb * 64 + lane * 2;
                const float* kp = sw + KT_OFF + k0;
                float a0[4], a1[4];
#pragma unroll
                for (int qq = 0; qq < 4; qq++) { a0[qq] = 0.f; a1[qq] = 0.f; }
#pragma unroll
                for (int j = 0; j < 16; j++) {
                    float2 kt2 = *(const float2*)(kp + j * KTS);
#pragma unroll
                    for (int qq = 0; qq < 4; qq++) {
                        a0[qq] = fmaf(kt2.x, qv[qq][j], a0[qq]);
                        a1[qq] = fmaf(kt2.y, qv[qq][j], a1[qq]);
                    }
                }
                const bool ok0 = (k0 + 0) < len;
                const bool ok1 = (k0 + 1) < len;
#pragma unroll
                for (int qq = 0; qq < 4; qq++) {
                    float e0 = ok0 ? ex2f(a0[qq]) : 0.f;
                    float e1 = ok1 ? ex2f(a1[qq]) : 0.f;
                    ee[kb][qq][0] = e0; ee[kb][qq][1] = e1;
                    z[qq] += e0 + e1;
                }
            } else {
#pragma unroll
                for (int qq = 0; qq < 4; qq++) { ee[kb][qq][0] = 0.f; ee[kb][qq][1] = 0.f; }
            }
        }

#pragma unroll
        for (int o = 16; o; o >>= 1) {
            z[0] += __shfl_xor_sync(0xffffffffu, z[0], o);
            z[1] += __shfl_xor_sync(0xffffffffu, z[1], o);
            z[2] += __shfl_xor_sync(0xffffffffu, z[2], o);
            z[3] += __shfl_xor_sync(0xffffffffu, z[3], o);
        }
        float inv[4];
#pragma unroll
        for (int qq = 0; qq < 4; qq++)
            inv[qq] = (qb + qq < len) ? __fdividef(1.0f, z[qq]) : 0.0f;
#pragma unroll
        for (int kb = 0; kb < 4; kb++) {
            if (kb < nb) {
#pragma unroll
                for (int qq = 0; qq < 4; qq++) {
                    wacc[kb][0] = fmaf(ee[kb][qq][0], inv[qq], wacc[kb][0]);
                    wacc[kb][1] = fmaf(ee[kb][qq][1], inv[qq], wacc[kb][1]);
                }
            }
        }
    }

#pragma unroll
    for (int kb = 0; kb < 4; kb++) {
        if (kb < nb) {
            int k = kb * 64 + lane * 2;
            if (k < Lc)     atomicAdd(&sw[WC_OFF + k],     wacc[kb][0]);
            if (k + 1 < Lc) atomicAdd(&sw[WC_OFF + k + 1], wacc[kb][1]);
        }
    }
    __syncthreads();

    // ---- phase 3: S[c] = sum_k wc[k] * V[k][c] ----
    {
        const int c = tid & 15, part = tid >> 4;
        float acc = 0.f;
        for (int k = part; k < len; k += 16)
            acc = fmaf(sw[WC_OFF + k], sw[VS_OFF + k * 16 + c], acc);
        sw[SP_OFF + part * 16 + c] = acc;
    }
    __syncthreads();
    if (tid < 16) {
        float s = 0.f;
#pragma unroll
        for (int p = 0; p < 16; p++) s += sw[SP_OFF + p * 16 + tid];
        sw[SP_OFF + tid] = s;
    }
    __syncthreads();

    // ---- phase 4 (fused): out[b][e] += inv*(S_head . Wf[e, h*16:]) (+ bf on h==0) ----
    if (tid < 64) {
        float acc = 0.f;
        const float* wfr = Wf + tid * 64 + h * 16;
#pragma unroll
        for (int i = 0; i < 16; i++)
            acc = fmaf(sw[SP_OFF + i], wfr[i], acc);
        const float lenf = (float)len;
        const float invd = 1.0f / (lenf + 1e-8f);
        float val = acc * invd;
        if (h == 0) val = fmaf(bf[tid], lenf * invd, val);
        atomicAdd(out + b * 64 + tid, val);
    }
}

extern "C" void kernel_launch(void* const* d_in, const int* in_sizes, int n_in,
                              void* d_out, int out_size) {
    const float* input   = (const float*)d_in[0];
    const int*   mask    = (const int*)d_in[1];
    const float* pos_enc = (const float*)d_in[2];
    const float* Wk      = (const float*)d_in[3];
    const float* bk      = (const float*)d_in[4];
    const float* Wv      = (const float*)d_in[5];
    const float* bv      = (const float*)d_in[6];
    const float* Wq      = (const float*)d_in[7];
    const float* bq      = (const float*)d_in[8];
    const float* Wf      = (const float*)d_in[9];
    const float* bf      = (const float*)d_in[10];
    float* out           = (float*)d_out;

    cudaMemsetAsync(out, 0, (size_t)Bc * Ec * sizeof(float), 0);

    len_kernel<<<Bc, 256>>>(mask);
    sort_kernel<<<1, 256>>>();

    const size_t smem1 = (size_t)SM1_F * sizeof(float);
    cudaFuncSetAttribute(attn_head_kernel,
                         cudaFuncAttributeMaxDynamicSharedMemorySize, (int)smem1);
    attn_head_kernel<<<Bc * 4, 256, smem1>>>(input, pos_enc,
                                             Wk, bk, Wv, bv, Wq, bq, Wf, bf, out);
}